// round 16
// baseline (speedup 1.0000x reference)
#include <cuda_runtime.h>
#include <cuda_bf16.h>
#include <math.h>
#include <stdint.h>

#define Bn 2
#define Tn 192
#define NBn 62
#define HID 256
#define DIN 512
#define NHEADS 8
#define HEADP 64
#define DSTATE 64
#define CONVDIM 640
#define PROJ 1160
#define NTOK (Bn*Tn*NBn)          /* 23808 */
#define CBMAX (124*192*192)
#define WIN_SZ  (4*PROJ*HID)
#define WOUT_SZ (4*HID*DIN)

/* ------------ device-global scratch (no cudaMalloc allowed) ------------ */
__device__ float g_Z  [NTOK*PROJ];
__device__ float g_xBC[NTOK*CONVDIM];
__device__ float g_dt [NTOK*NHEADS];
__device__ float g_CB [CBMAX];           /* stored [seq][l][s] */
__device__ float g_y  [NTOK*DIN];        /* ssd -> gate only */
__device__ __nv_bfloat16 g_xnh[NTOK*HID], g_xnl[NTOK*HID];   /* split rmsnorm out */
__device__ __nv_bfloat16 g_yh [NTOK*DIN], g_yl [NTOK*DIN];   /* split gate out    */
__device__ __nv_bfloat16 g_Whi[WIN_SZ + WOUT_SZ];
__device__ __nv_bfloat16 g_Wlo[WIN_SZ + WOUT_SZ];

/* token (seq,t) -> offset into the (B,T,NB,H) activation tensor */
__device__ __forceinline__ int xoff(int axis, int seq, int t)
{
    if (axis == 0) {
        int b = seq / NBn, nb = seq - b*NBn;
        return ((b*Tn + t)*NBn + nb)*HID;
    }
    return (seq*NBn + t)*HID;
}

__device__ __forceinline__ uint32_t smem_u32(const void* p)
{
    uint32_t a;
    asm("{ .reg .u64 t; cvta.to.shared.u64 t, %1; cvt.u32.u64 %0, t; }" : "=r"(a) : "l"(p));
    return a;
}
__device__ __forceinline__ void mma16(float* d, const uint32_t* a,
                                      uint32_t b0, uint32_t b1)
{
    asm volatile("mma.sync.aligned.m16n8k16.row.col.f32.bf16.bf16.f32 "
        "{%0,%1,%2,%3}, {%4,%5,%6,%7}, {%8,%9}, {%0,%1,%2,%3};"
        : "+f"(d[0]), "+f"(d[1]), "+f"(d[2]), "+f"(d[3])
        : "r"(a[0]), "r"(a[1]), "r"(a[2]), "r"(a[3]), "r"(b0), "r"(b1));
}
__device__ __forceinline__ void ldm4(uint32_t* r, uint32_t a)
{
    asm volatile("ldmatrix.sync.aligned.m8n8.x4.shared.b16 {%0,%1,%2,%3}, [%4];"
        : "=r"(r[0]), "=r"(r[1]), "=r"(r[2]), "=r"(r[3]) : "r"(a));
}
__device__ __forceinline__ void ldm4t(uint32_t* r, uint32_t a)
{
    asm volatile("ldmatrix.sync.aligned.m8n8.x4.trans.shared.b16 {%0,%1,%2,%3}, [%4];"
        : "=r"(r[0]), "=r"(r[1]), "=r"(r[2]), "=r"(r[3]) : "r"(a));
}

/* --------- 1. strided gather + RMSNorm(256), split-bf16 output --------- */
__global__ void k_rmsnorm(const float* __restrict__ x, const float* __restrict__ w,
                          int axis, int L)
{
    int tok = blockIdx.x*8 + (threadIdx.x >> 5);
    if (tok >= NTOK) return;
    int lane = threadIdx.x & 31;
    int seq = tok / L, t = tok - seq*L;
    const float* xp = x + xoff(axis, seq, t);
    float v[8]; float ss = 0.f;
#pragma unroll
    for (int i = 0; i < 8; i++) { v[i] = xp[lane + 32*i]; ss += v[i]*v[i]; }
#pragma unroll
    for (int o = 16; o; o >>= 1) ss += __shfl_xor_sync(0xffffffffu, ss, o);
    float r = rsqrtf(ss*(1.f/HID) + 1e-6f);
#pragma unroll
    for (int i = 0; i < 8; i++) {
        float y = v[i]*r*w[lane + 32*i];
        __nv_bfloat16 hh = __float2bfloat16(y);
        g_xnh[(size_t)tok*HID + lane + 32*i] = hh;
        g_xnl[(size_t)tok*HID + lane + 32*i] = __float2bfloat16(y - __bfloat162float(hh));
    }
}

/* ---- weight transpose + bf16 hi/lo split: W[K][N] -> Whi/Wlo[N][K] ---- */
__global__ void k_splitw(const float* __restrict__ W, __nv_bfloat16* __restrict__ Whi,
                         __nv_bfloat16* __restrict__ Wlo, int K, int N)
{
    __shared__ float t[32][33];
    int n0 = blockIdx.x*32, k0 = blockIdx.y*32;
    int x = threadIdx.x, y = threadIdx.y;
#pragma unroll
    for (int i = 0; i < 32; i += 8) {
        int k = k0 + y + i, n = n0 + x;
        t[y+i][x] = (k < K && n < N) ? W[k*N + n] : 0.f;
    }
    __syncthreads();
#pragma unroll
    for (int i = 0; i < 32; i += 8) {
        int n = n0 + y + i, k = k0 + x;
        if (n < N && k < K) {
            float v = t[x][y+i];
            __nv_bfloat16 h = __float2bfloat16(v);
            Whi[(size_t)n*K + k] = h;
            Wlo[(size_t)n*K + k] = __float2bfloat16(v - __bfloat162float(h));
        }
    }
}

/* - 2/8. bf16-split HMMA GEMM, 128x64 tile, 2 CTAs/SM; both operands
 * pre-split -> mainloop is copies + ldmatrix + mma only.                */
#define RS   80
#define AHI  0
#define ALO  (128*RS)
#define BHI  (2*128*RS)
#define BLO  (2*128*RS + 64*RS)
#define GSM  (2*128*RS + 2*64*RS)  /* 30720 B */
__global__ void __launch_bounds__(256, 2)
k_mma(const __nv_bfloat16* __restrict__ Ahi, const __nv_bfloat16* __restrict__ Alo,
      const __nv_bfloat16* __restrict__ Whi, const __nv_bfloat16* __restrict__ Wlo,
      int N, int K, int mode, float* xout, int axis, int L)
{
    extern __shared__ char sm[];
    uint32_t sb = smem_u32(sm);
    int m0 = blockIdx.y*128, n0 = blockIdx.x*64;
    int tid = threadIdx.x, lane = tid & 31, wid = tid >> 5;
    int wm = (wid & 3)*32, wn = (wid >> 2)*32;
    int row0 = tid >> 3, c4 = (tid & 7)*4;

    int q = lane >> 3, r8 = lane & 7;
    uint32_t aoff = (uint32_t)((wm + (q & 1)*8 + r8)*RS + (q >> 1)*16);
    uint32_t boff = (uint32_t)(BHI + (wn + (q >> 1)*8 + r8)*RS + (q & 1)*16);

    float acc[2][4][4];
#pragma unroll
    for (int mi = 0; mi < 2; mi++)
#pragma unroll
        for (int ni = 0; ni < 4; ni++)
#pragma unroll
            for (int p = 0; p < 4; p++) acc[mi][ni][p] = 0.f;

    int nch = K >> 5;
    uint2 pah[4], pal[4], pbh[2], pbl[2];
#pragma unroll
    for (int i = 0; i < 4; i++) {
        size_t o = (size_t)(m0 + row0 + 32*i)*K + c4;
        pah[i] = *(const uint2*)&Ahi[o];
        pal[i] = *(const uint2*)&Alo[o];
    }
#pragma unroll
    for (int i = 0; i < 2; i++) {
        int n = n0 + row0 + 32*i;
        if (n < N) {
            pbh[i] = *(const uint2*)&Whi[(size_t)n*K + c4];
            pbl[i] = *(const uint2*)&Wlo[(size_t)n*K + c4];
        } else { pbh[i] = make_uint2(0,0); pbl[i] = make_uint2(0,0); }
    }

    for (int c = 0; c < nch; c++) {
#pragma unroll
        for (int i = 0; i < 4; i++) {
            int r = row0 + 32*i;
            *(uint2*)(sm + AHI + r*RS + c4*2) = pah[i];
            *(uint2*)(sm + ALO + r*RS + c4*2) = pal[i];
        }
#pragma unroll
        for (int i = 0; i < 2; i++) {
            int r = row0 + 32*i;
            *(uint2*)(sm + BHI + r*RS + c4*2) = pbh[i];
            *(uint2*)(sm + BLO + r*RS + c4*2) = pbl[i];
        }
        __syncthreads();
        if (c + 1 < nch) {
            int kt = (c+1)*32;
#pragma unroll
            for (int i = 0; i < 4; i++) {
                size_t o = (size_t)(m0 + row0 + 32*i)*K + kt + c4;
                pah[i] = *(const uint2*)&Ahi[o];
                pal[i] = *(const uint2*)&Alo[o];
            }
#pragma unroll
            for (int i = 0; i < 2; i++) {
                int n = n0 + row0 + 32*i;
                if (n < N) {
                    pbh[i] = *(const uint2*)&Whi[(size_t)n*K + kt + c4];
                    pbl[i] = *(const uint2*)&Wlo[(size_t)n*K + kt + c4];
                } else { pbh[i] = make_uint2(0,0); pbl[i] = make_uint2(0,0); }
            }
        }
#pragma unroll
        for (int kb = 0; kb < 2; kb++) {
            uint32_t ah[2][4], al[2][4];
            ldm4(ah[0], sb + AHI + aoff + kb*32);
            ldm4(ah[1], sb + AHI + aoff + 16*RS + kb*32);
            ldm4(al[0], sb + ALO + aoff + kb*32);
            ldm4(al[1], sb + ALO + aoff + 16*RS + kb*32);
#pragma unroll
            for (int np = 0; np < 2; np++) {
                uint32_t bh[4], bl[4];
                ldm4(bh, sb + boff + np*16*RS + kb*32);
                ldm4(bl, sb + (boff + 64*RS) + np*16*RS + kb*32);
#pragma unroll
                for (int mi = 0; mi < 2; mi++) {
                    mma16(acc[mi][np*2+0], ah[mi], bh[0], bh[1]);
                    mma16(acc[mi][np*2+0], ah[mi], bl[0], bl[1]);
                    mma16(acc[mi][np*2+0], al[mi], bh[0], bh[1]);
                    mma16(acc[mi][np*2+1], ah[mi], bh[2], bh[3]);
                    mma16(acc[mi][np*2+1], ah[mi], bl[2], bl[3]);
                    mma16(acc[mi][np*2+1], al[mi], bh[2], bh[3]);
                }
            }
        }
        __syncthreads();
    }

    int cl = (lane & 3)*2, rw = lane >> 2;
    if (mode == 0) {
#pragma unroll
        for (int mi = 0; mi < 2; mi++)
#pragma unroll
            for (int ni = 0; ni < 4; ni++) {
                int col = n0 + wn + ni*8 + cl;
                if (col < N) {
                    int r = m0 + wm + mi*16 + rw;
                    *(float2*)&g_Z[(size_t)r*PROJ + col] =
                        make_float2(acc[mi][ni][0], acc[mi][ni][1]);
                    *(float2*)&g_Z[(size_t)(r+8)*PROJ + col] =
                        make_float2(acc[mi][ni][2], acc[mi][ni][3]);
                }
            }
    } else {
#pragma unroll
        for (int mi = 0; mi < 2; mi++)
#pragma unroll
            for (int ni = 0; ni < 4; ni++) {
                int col = n0 + wn + ni*8 + cl;
#pragma unroll
                for (int half = 0; half < 2; half++) {
                    int r = m0 + wm + mi*16 + rw + half*8;
                    int seq = r / L, t = r - seq*L;
                    float* op = xout + xoff(axis, seq, t) + col;
                    float2 o = *(const float2*)op;
                    o.x += acc[mi][ni][2*half];
                    o.y += acc[mi][ni][2*half+1];
                    *(float2*)op = o;
                }
            }
    }
}

/* ------- 3. causal conv(K=4)+SiLU + softplus(dt); div-free indexing ---- */
__global__ void k_convdt(const float* __restrict__ Wc, const float* __restrict__ bc,
                         const float* __restrict__ dtb)
{
    int c   = blockIdx.x*256 + threadIdx.x;
    int t   = blockIdx.y;
    int seq = blockIdx.z;
    int L   = gridDim.y;
    if (c >= CONVDIM + NHEADS) return;
    size_t tok = (size_t)seq*L + t;
    if (c < CONVDIM) {
        const float* zp = g_Z + tok*PROJ + DIN + c;
        float acc = bc[c];
        float4 w = *(const float4*)&Wc[c*4];
        if (t >= 3) {
            acc += w.x*zp[-3*PROJ] + w.y*zp[-2*PROJ] + w.z*zp[-PROJ] + w.w*zp[0];
        } else {
            if (t >= 2) acc += w.y*zp[-2*PROJ];
            if (t >= 1) acc += w.z*zp[-PROJ];
            acc += w.w*zp[0];
        }
        g_xBC[tok*CONVDIM + c] = __fdividef(acc, 1.f + __expf(-acc));
    } else {
        int h = c - CONVDIM;
        float v = g_Z[tok*PROJ + DIN + CONVDIM + h] + dtb[h];
        g_dt[tok*NHEADS + h] = (v > 20.f) ? v : log1pf(__expf(v));
    }
}

/* --------- 5. CB stored [l][s]: g_CB[seq][l][s] = C[l].B[s] ------------ */
__global__ void k_cb(int L)
{
    __shared__ __align__(16) float Ct[64][68], Bt[64][68];
    int seq = blockIdx.x;
    int l0 = blockIdx.y*64, s0 = blockIdx.z*64;
    int tid = threadIdx.x;
    int n = tid & 63, r = tid >> 6;
#pragma unroll 4
    for (int i = 0; i < 16; i++) {
        int row = r + 4*i;
        int gl = l0 + row, gs = s0 + row;
        Ct[n][row] = (gl < L) ? g_xBC[(size_t)(seq*L + gl)*CONVDIM + DIN + DSTATE + n] : 0.f;
        Bt[n][row] = (gs < L) ? g_xBC[(size_t)(seq*L + gs)*CONVDIM + DIN + n]          : 0.f;
    }
    __syncthreads();
    int tx = tid & 15, ty = tid >> 4;
    float acc[4][4] = {};
#pragma unroll 8
    for (int k = 0; k < 64; k++) {
        float4 a = *(const float4*)&Ct[k][ty*4];
        float4 b = *(const float4*)&Bt[k][tx*4];
        acc[0][0]+=a.x*b.x; acc[0][1]+=a.x*b.y; acc[0][2]+=a.x*b.z; acc[0][3]+=a.x*b.w;
        acc[1][0]+=a.y*b.x; acc[1][1]+=a.y*b.y; acc[1][2]+=a.y*b.z; acc[1][3]+=a.y*b.w;
        acc[2][0]+=a.z*b.x; acc[2][1]+=a.z*b.y; acc[2][2]+=a.z*b.z; acc[2][3]+=a.z*b.w;
        acc[3][0]+=a.w*b.x; acc[3][1]+=a.w*b.y; acc[3][2]+=a.w*b.z; acc[3][3]+=a.w*b.w;
    }
#pragma unroll
    for (int i = 0; i < 4; i++) {
        int gl = l0 + ty*4 + i;
#pragma unroll
        for (int j = 0; j < 4; j++) {
            int gs = s0 + tx*4 + j;
            if (gl < L && gs < L) g_CB[(size_t)(seq*L + gl)*L + gs] = acc[i][j];
        }
    }
}

/* --- 6. SSD via split-bf16 HMMA (W [l][s] A row-major; X [s][p] .trans) */
#define SSR 72
__global__ void __launch_bounds__(256)
k_ssd(const float* __restrict__ Alog, int L)
{
    __shared__ float cum[192], ecum[192], dts[192];
    __shared__ float uf[64], ub[64], vbuf[64];
    __shared__ __align__(16) __nv_bfloat16 Wh[64][SSR], Wl[64][SSR];
    __shared__ __align__(16) __nv_bfloat16 Xh[64][SSR], Xl[64][SSR];
    int seq = blockIdx.x, h = blockIdx.y, l0 = blockIdx.z*64;
    int tid = threadIdx.x, lane = tid & 31, wid = tid >> 5;
    float A = -expf(Alog[h]);
    int lend = min(l0 + 63, L - 1);

    for (int t = tid; t < L; t += 256) {
        float d = g_dt[(seq*L + t)*NHEADS + h];
        dts[t] = d;
        cum[t] = d*A;
    }
    __syncthreads();
    for (int off = 1; off < L; off <<= 1) {
        float v = 0.f;
        if (tid < L && tid >= off) v = cum[tid - off];
        __syncthreads();
        if (tid < L) cum[tid] += v;
        __syncthreads();
    }
    for (int t = tid; t < L; t += 256) ecum[t] = cum[t] - dts[t]*A;
    __syncthreads();
    if (tid < 64) {
        int gl = l0 + tid;
        uf[tid] = (gl < L) ? __expf(cum[gl] - cum[l0])     : 0.f;
        ub[tid] = (gl < L) ? __expf(ecum[lend] - ecum[gl]) : 0.f;
    }
    __syncthreads();

    int wm = (wid & 3)*16, wn = (wid >> 2)*32;
    int q = lane >> 3, r8 = lane & 7;
    uint32_t sbW = smem_u32(Wh), sbWl = smem_u32(Wl);
    uint32_t sbX = smem_u32(Xh), sbXl = smem_u32(Xl);
    uint32_t aoff = (uint32_t)((wm + (q & 1)*8 + r8)*(SSR*2) + (q >> 1)*16);
    uint32_t brow = (uint32_t)(((q & 1)*8 + r8)*(SSR*2));
    uint32_t bcol = (uint32_t)((wn + (q >> 1)*8)*2);

    int fc = tid & 63, fr = tid >> 6;
    float acc[4][4] = {};

    for (int s0 = 0; s0 < L; s0 += 64) {
        int diag = (s0 == l0);
        if (!diag && tid < 64) {
            int gs = s0 + tid;
            float v = 0.f;
            if (gs < L) {
                v = (s0 < l0) ? __expf(cum[l0] - cum[gs])
                              : __expf(ecum[gs] - ecum[lend]);
                v *= dts[gs];
            }
            vbuf[tid] = v;
        }
#pragma unroll 4
        for (int i = 0; i < 16; i++) {
            int s = fr + 4*i;
            int gs = s0 + s;
            float v = (gs < L) ? g_xBC[(size_t)(seq*L + gs)*CONVDIM + h*HEADP + fc] : 0.f;
            __nv_bfloat16 hh = __float2bfloat16(v);
            Xh[s][fc] = hh;
            Xl[s][fc] = __float2bfloat16(v - __bfloat162float(hh));
        }
        if (!diag) __syncthreads();

        if (diag) {
#pragma unroll 4
            for (int i = 0; i < 16; i++) {
                int lW = fr + 4*i, sW = fc;
                int gl = l0 + lW, gs = s0 + sW;
                float w = 0.f;
                if (gl < L && gs < L) {
                    float cb = g_CB[(size_t)(seq*L + gl)*L + gs];
                    float e;
                    if (gs < gl)       e = __expf(cum[gl] - cum[gs]);
                    else if (gs == gl) e = 2.f;
                    else               e = __expf(ecum[gs] - ecum[gl]);
                    w = cb * e * dts[gs];
                }
                __nv_bfloat16 hh = __float2bfloat16(w);
                Wh[lW][sW] = hh;
                Wl[lW][sW] = __float2bfloat16(w - __bfloat162float(hh));
            }
        } else {
            const float* uu = (s0 < l0) ? uf : ub;
#pragma unroll 4
            for (int i = 0; i < 16; i++) {
                int lW = fr + 4*i, sW = fc;
                int gl = l0 + lW, gs = s0 + sW;
                float w = 0.f;
                if (gl < L && gs < L)
                    w = g_CB[(size_t)(seq*L + gl)*L + gs] * vbuf[sW] * uu[lW];
                __nv_bfloat16 hh = __float2bfloat16(w);
                Wh[lW][sW] = hh;
                Wl[lW][sW] = __float2bfloat16(w - __bfloat162float(hh));
            }
        }
        __syncthreads();
#pragma unroll
        for (int kb = 0; kb < 4; kb++) {
            uint32_t ah[4], al[4];
            ldm4(ah, sbW  + aoff + kb*32);
            ldm4(al, sbWl + aoff + kb*32);
#pragma unroll
            for (int nh = 0; nh < 2; nh++) {
                uint32_t bh[4], bl[4];
                uint32_t bo = brow + kb*16*(SSR*2) + bcol + nh*32;
                ldm4t(bh, sbX  + bo);
                ldm4t(bl, sbXl + bo);
                mma16(acc[nh*2+0], ah, bh[0], bh[1]);
                mma16(acc[nh*2+0], ah, bl[0], bl[1]);
                mma16(acc[nh*2+0], al, bh[0], bh[1]);
                mma16(acc[nh*2+1], ah, bh[2], bh[3]);
                mma16(acc[nh*2+1], ah, bl[2], bl[3]);
                mma16(acc[nh*2+1], al, bh[2], bh[3]);
            }
        }
        __syncthreads();
    }

    int rw = lane >> 2, cl = (lane & 3)*2;
#pragma unroll
    for (int half = 0; half < 2; half++) {
        int gl = l0 + wm + half*8 + rw;
        if (gl < L) {
            float* yp = g_y + (size_t)(seq*L + gl)*DIN + h*HEADP + wn + cl;
#pragma unroll
            for (int nf = 0; nf < 4; nf++)
                *(float2*)&yp[nf*8] = make_float2(acc[nf][2*half], acc[nf][2*half+1]);
        }
    }
}

/* -- 7. (y + D*xh)*silu(z), RMSNorm(512)*gn_w, split-bf16 output -------- */
__global__ void k_gate(const float* __restrict__ Dv, const float* __restrict__ gnw)
{
    __shared__ float red[8];
    int tok = blockIdx.x, tid = threadIdx.x;
    float v[2]; float ss = 0.f;
#pragma unroll
    for (int i = 0; i < 2; i++) {
        int d = tid + 256*i;
        float y = g_y[(size_t)tok*DIN + d] + Dv[d >> 6]*g_xBC[(size_t)tok*CONVDIM + d];
        float z = g_Z[(size_t)tok*PROJ + d];
        y *= __fdividef(z, 1.f + __expf(-z));
        v[i] = y; ss += y*y;
    }
#pragma unroll
    for (int o = 16; o; o >>= 1) ss += __shfl_xor_sync(0xffffffffu, ss, o);
    if ((tid & 31) == 0) red[tid >> 5] = ss;
    __syncthreads();
    if (tid < 32) {
        float s = (tid < 8) ? red[tid] : 0.f;
#pragma unroll
        for (int o = 4; o; o >>= 1) s += __shfl_xor_sync(0xffffffffu, s, o);
        if (tid == 0) red[0] = s;
    }
    __syncthreads();
    float r = rsqrtf(red[0]*(1.f/DIN) + 1e-6f);
#pragma unroll
    for (int i = 0; i < 2; i++) {
        int d = tid + 256*i;
        float y = v[i]*r*gnw[d];
        __nv_bfloat16 hh = __float2bfloat16(y);
        g_yh[(size_t)tok*DIN + d] = hh;
        g_yl[(size_t)tok*DIN + d] = __float2bfloat16(y - __bfloat162float(hh));
    }
}

/* ----------------------------- host side ------------------------------ */
static __nv_bfloat16 *h_whi, *h_wlo, *h_xnh, *h_xnl, *h_yh, *h_yl;

static void run_call(float* out, const float* const* P, int li, int axis, int idx)
{
    int L = (axis == 0) ? Tn : NBn;
    int nseq = NTOK / L;
    int lt = (L + 63)/64;

    k_rmsnorm<<<NTOK/8, 256>>>(out, P[0] + li*HID, axis, L);
    k_mma<<<dim3((PROJ + 63)/64, NTOK/128), 256, GSM>>>(
        h_xnh, h_xnl,
        h_whi + (size_t)idx*PROJ*HID, h_wlo + (size_t)idx*PROJ*HID,
        PROJ, HID, 0, nullptr, axis, L);
    k_convdt<<<dim3(3, L, nseq), 256>>>(
        P[2] + li*CONVDIM*4, P[3] + li*CONVDIM, P[4] + li*NHEADS);
    k_cb<<<dim3(nseq, lt, lt), 256>>>(L);
    k_ssd<<<dim3(nseq, NHEADS, lt), 256>>>(P[5] + li*NHEADS, L);
    k_gate<<<NTOK, 256>>>(P[6] + li*NHEADS, P[7] + li*DIN);
    k_mma<<<dim3(HID/64, NTOK/128), 256, GSM>>>(
        h_yh, h_yl,
        h_whi + WIN_SZ + (size_t)idx*HID*DIN, h_wlo + WIN_SZ + (size_t)idx*HID*DIN,
        HID, DIN, 1, out, axis, L);
}

extern "C" void kernel_launch(void* const* d_in, const int* in_sizes, int n_in,
                              void* d_out, int out_size)
{
    static int smem_set = 0;
    if (!smem_set) {
        cudaFuncSetAttribute(k_mma, cudaFuncAttributeMaxDynamicSharedMemorySize, GSM);
        smem_set = 1;
    }

    float* out = (float*)d_out;
    cudaMemcpyAsync(out, d_in[0], (size_t)out_size*sizeof(float),
                    cudaMemcpyDeviceToDevice);
    const float* tp[9]; const float* bp[9];
    for (int i = 0; i < 9; i++) {
        tp[i] = (const float*)d_in[1 + i];
        bp[i] = (const float*)d_in[10 + i];
    }
    cudaGetSymbolAddress((void**)&h_whi, g_Whi);
    cudaGetSymbolAddress((void**)&h_wlo, g_Wlo);
    cudaGetSymbolAddress((void**)&h_xnh, g_xnh);
    cudaGetSymbolAddress((void**)&h_xnl, g_xnl);
    cudaGetSymbolAddress((void**)&h_yh,  g_yh);
    cudaGetSymbolAddress((void**)&h_yl,  g_yl);

    for (int ax = 0; ax < 2; ax++) {
        const float* const* P = ax ? bp : tp;
        for (int li = 0; li < 2; li++) {
            int idx = ax*2 + li;
            k_splitw<<<dim3((PROJ+31)/32, (HID+31)/32), dim3(32,8)>>>(
                P[1] + li*HID*PROJ,
                h_whi + (size_t)idx*PROJ*HID, h_wlo + (size_t)idx*PROJ*HID, HID, PROJ);
            k_splitw<<<dim3((HID+31)/32, (DIN+31)/32), dim3(32,8)>>>(
                P[8] + li*DIN*HID,
                h_whi + WIN_SZ + (size_t)idx*HID*DIN, h_wlo + WIN_SZ + (size_t)idx*HID*DIN,
                DIN, HID);
        }
    }

    run_call(out, tp, 0, 0, 0);
    run_call(out, bp, 0, 1, 2);
    run_call(out, tp, 1, 0, 1);
    run_call(out, bp, 1, 1, 3);
}

// round 17
// speedup vs baseline: 1.0649x; 1.0649x over previous
#include <cuda_runtime.h>
#include <cuda_bf16.h>
#include <math.h>
#include <stdint.h>

#define Bn 2
#define Tn 192
#define NBn 62
#define HID 256
#define DIN 512
#define NHEADS 8
#define HEADP 64
#define DSTATE 64
#define CONVDIM 640
#define PROJ 1160
#define NTOK (Bn*Tn*NBn)          /* 23808 */
#define CBMAX (124*192*192)
#define WIN_SZ  (4*PROJ*HID)
#define WOUT_SZ (4*HID*DIN)

/* ------------ device-global scratch (no cudaMalloc allowed) ------------ */
__device__ float g_xn [NTOK*HID];
__device__ float g_Z  [NTOK*PROJ];
__device__ float g_xBC[NTOK*CONVDIM];
__device__ float g_dt [NTOK*NHEADS];
__device__ float g_CB [CBMAX];           /* stored [seq][l][s] */
__device__ float g_y  [NTOK*DIN];
__device__ __nv_bfloat16 g_Whi[WIN_SZ + WOUT_SZ];
__device__ __nv_bfloat16 g_Wlo[WIN_SZ + WOUT_SZ];

/* token (seq,t) -> offset into the (B,T,NB,H) activation tensor */
__device__ __forceinline__ int xoff(int axis, int seq, int t)
{
    if (axis == 0) {
        int b = seq / NBn, nb = seq - b*NBn;
        return ((b*Tn + t)*NBn + nb)*HID;
    }
    return (seq*NBn + t)*HID;
}

__device__ __forceinline__ uint32_t smem_u32(const void* p)
{
    uint32_t a;
    asm("{ .reg .u64 t; cvta.to.shared.u64 t, %1; cvt.u32.u64 %0, t; }" : "=r"(a) : "l"(p));
    return a;
}
__device__ __forceinline__ uint32_t bfpk(float lo, float hi)
{
    uint32_t r;
    asm("cvt.rn.bf16x2.f32 %0, %1, %2;" : "=r"(r) : "f"(hi), "f"(lo));
    return r;
}
__device__ __forceinline__ void mma16(float* d, const uint32_t* a,
                                      uint32_t b0, uint32_t b1)
{
    asm volatile("mma.sync.aligned.m16n8k16.row.col.f32.bf16.bf16.f32 "
        "{%0,%1,%2,%3}, {%4,%5,%6,%7}, {%8,%9}, {%0,%1,%2,%3};"
        : "+f"(d[0]), "+f"(d[1]), "+f"(d[2]), "+f"(d[3])
        : "r"(a[0]), "r"(a[1]), "r"(a[2]), "r"(a[3]), "r"(b0), "r"(b1));
}
__device__ __forceinline__ void ldm4(uint32_t* r, uint32_t a)
{
    asm volatile("ldmatrix.sync.aligned.m8n8.x4.shared.b16 {%0,%1,%2,%3}, [%4];"
        : "=r"(r[0]), "=r"(r[1]), "=r"(r[2]), "=r"(r[3]) : "r"(a));
}
__device__ __forceinline__ void ldm4t(uint32_t* r, uint32_t a)
{
    asm volatile("ldmatrix.sync.aligned.m8n8.x4.trans.shared.b16 {%0,%1,%2,%3}, [%4];"
        : "=r"(r[0]), "=r"(r[1]), "=r"(r[2]), "=r"(r[3]) : "r"(a));
}

/* ------------------ 1. strided gather + RMSNorm(256) ------------------ */
__global__ void k_rmsnorm(const float* __restrict__ x, const float* __restrict__ w,
                          int axis, int L)
{
    int tok = blockIdx.x*8 + (threadIdx.x >> 5);
    if (tok >= NTOK) return;
    int lane = threadIdx.x & 31;
    int seq = tok / L, t = tok - seq*L;
    const float* xp = x + xoff(axis, seq, t);
    float v[8]; float ss = 0.f;
#pragma unroll
    for (int i = 0; i < 8; i++) { v[i] = xp[lane + 32*i]; ss += v[i]*v[i]; }
#pragma unroll
    for (int o = 16; o; o >>= 1) ss += __shfl_xor_sync(0xffffffffu, ss, o);
    float r = rsqrtf(ss*(1.f/HID) + 1e-6f);
    float* op = g_xn + tok*HID;
#pragma unroll
    for (int i = 0; i < 8; i++) op[lane + 32*i] = v[i]*r*w[lane + 32*i];
}

/* ---- weight transpose + bf16 hi/lo split: W[K][N] -> Whi/Wlo[N][K] ---- */
__global__ void k_splitw(const float* __restrict__ W, __nv_bfloat16* __restrict__ Whi,
                         __nv_bfloat16* __restrict__ Wlo, int K, int N)
{
    __shared__ float t[32][33];
    int n0 = blockIdx.x*32, k0 = blockIdx.y*32;
    int x = threadIdx.x, y = threadIdx.y;
#pragma unroll
    for (int i = 0; i < 32; i += 8) {
        int k = k0 + y + i, n = n0 + x;
        t[y+i][x] = (k < K && n < N) ? W[k*N + n] : 0.f;
    }
    __syncthreads();
#pragma unroll
    for (int i = 0; i < 32; i += 8) {
        int n = n0 + y + i, k = k0 + x;
        if (n < N && k < K) {
            float v = t[x][y+i];
            __nv_bfloat16 h = __float2bfloat16(v);
            Whi[(size_t)n*K + k] = h;
            Wlo[(size_t)n*K + k] = __float2bfloat16(v - __bfloat162float(h));
        }
    }
}

/* - 2/8. bf16-split HMMA GEMM, 128x64 tile, DOUBLE-BUFFERED smem -------
 * One __syncthreads per K-chunk; split+store of chunk c+1 overlaps the
 * MMAs of chunk c (disjoint buffers). Layout identical to R15 (RS=80). */
#define RS   80
#define AHI  0
#define ALO  (128*RS)
#define BHI  (2*128*RS)
#define BLO  (2*128*RS + 64*RS)
#define BUF  (2*128*RS + 2*64*RS)  /* 30720 B per buffer */
#define GSM  (2*BUF)               /* 61440 B */
__global__ void __launch_bounds__(256, 2)
k_mma(int asel, const __nv_bfloat16* __restrict__ Whi,
      const __nv_bfloat16* __restrict__ Wlo, int N, int K,
      int mode, float* xout, int axis, int L)
{
    extern __shared__ char sm[];
    uint32_t sb = smem_u32(sm);
    const float* A = asel ? g_y : g_xn;
    int m0 = blockIdx.y*128, n0 = blockIdx.x*64;
    int tid = threadIdx.x, lane = tid & 31, wid = tid >> 5;
    int wm = (wid & 3)*32, wn = (wid >> 2)*32;
    int row0 = tid >> 3, c4 = (tid & 7)*4;

    int q = lane >> 3, r8 = lane & 7;
    uint32_t aoff = (uint32_t)((wm + (q & 1)*8 + r8)*RS + (q >> 1)*16);
    uint32_t boff = (uint32_t)(BHI + (wn + (q >> 1)*8 + r8)*RS + (q & 1)*16);

    float acc[2][4][4];
#pragma unroll
    for (int mi = 0; mi < 2; mi++)
#pragma unroll
        for (int ni = 0; ni < 4; ni++)
#pragma unroll
            for (int p = 0; p < 4; p++) acc[mi][ni][p] = 0.f;

    int nch = K >> 5;
    float4 pa[4]; uint2 pbh[2], pbl[2];

#define FETCH(kt) do {                                                        \
    _Pragma("unroll")                                                         \
    for (int i = 0; i < 4; i++)                                               \
        pa[i] = *(const float4*)&A[(size_t)(m0 + row0 + 32*i)*K + (kt) + c4]; \
    _Pragma("unroll")                                                         \
    for (int i = 0; i < 2; i++) {                                             \
        int n = n0 + row0 + 32*i;                                             \
        if (n < N) {                                                          \
            pbh[i] = *(const uint2*)&Whi[(size_t)n*K + (kt) + c4];            \
            pbl[i] = *(const uint2*)&Wlo[(size_t)n*K + (kt) + c4];            \
        } else { pbh[i] = make_uint2(0,0); pbl[i] = make_uint2(0,0); }        \
    } } while (0)

#define STORE(b) do {                                                         \
    char* bp_ = sm + (uint32_t)(b)*BUF;                                       \
    _Pragma("unroll")                                                         \
    for (int i = 0; i < 4; i++) {                                             \
        int r = row0 + 32*i;                                                  \
        float4 v = pa[i];                                                     \
        float h0 = __bfloat162float(__float2bfloat16(v.x));                   \
        float h1 = __bfloat162float(__float2bfloat16(v.y));                   \
        float h2 = __bfloat162float(__float2bfloat16(v.z));                   \
        float h3 = __bfloat162float(__float2bfloat16(v.w));                   \
        uint2 uh = make_uint2(bfpk(v.x, v.y), bfpk(v.z, v.w));                \
        uint2 ul = make_uint2(bfpk(v.x - h0, v.y - h1), bfpk(v.z - h2, v.w - h3)); \
        *(uint2*)(bp_ + AHI + r*RS + c4*2) = uh;                              \
        *(uint2*)(bp_ + ALO + r*RS + c4*2) = ul;                              \
    }                                                                         \
    _Pragma("unroll")                                                         \
    for (int i = 0; i < 2; i++) {                                             \
        int r = row0 + 32*i;                                                  \
        *(uint2*)(bp_ + BHI + r*RS + c4*2) = pbh[i];                          \
        *(uint2*)(bp_ + BLO + r*RS + c4*2) = pbl[i];                          \
    } } while (0)

    FETCH(0);
    STORE(0);
    __syncthreads();

    for (int c = 0; c < nch; c++) {
        if (c + 1 < nch) FETCH((c+1)*32);
        uint32_t bb = sb + (uint32_t)(c & 1)*BUF;
#pragma unroll
        for (int kb = 0; kb < 2; kb++) {
            uint32_t ah[2][4], al[2][4];
            ldm4(ah[0], bb + AHI + aoff + kb*32);
            ldm4(ah[1], bb + AHI + aoff + 16*RS + kb*32);
            ldm4(al[0], bb + ALO + aoff + kb*32);
            ldm4(al[1], bb + ALO + aoff + 16*RS + kb*32);
#pragma unroll
            for (int np = 0; np < 2; np++) {
                uint32_t bh[4], bl[4];
                ldm4(bh, bb + boff + np*16*RS + kb*32);
                ldm4(bl, bb + (boff + 64*RS) + np*16*RS + kb*32);
#pragma unroll
                for (int mi = 0; mi < 2; mi++) {
                    mma16(acc[mi][np*2+0], ah[mi], bh[0], bh[1]);
                    mma16(acc[mi][np*2+0], ah[mi], bl[0], bl[1]);
                    mma16(acc[mi][np*2+0], al[mi], bh[0], bh[1]);
                    mma16(acc[mi][np*2+1], ah[mi], bh[2], bh[3]);
                    mma16(acc[mi][np*2+1], ah[mi], bl[2], bl[3]);
                    mma16(acc[mi][np*2+1], al[mi], bh[2], bh[3]);
                }
            }
        }
        if (c + 1 < nch) STORE((c+1) & 1);
        __syncthreads();
    }
#undef FETCH
#undef STORE

    int cl = (lane & 3)*2, rw = lane >> 2;
    if (mode == 0) {
#pragma unroll
        for (int mi = 0; mi < 2; mi++)
#pragma unroll
            for (int ni = 0; ni < 4; ni++) {
                int col = n0 + wn + ni*8 + cl;
                if (col < N) {
                    int r = m0 + wm + mi*16 + rw;
                    *(float2*)&g_Z[(size_t)r*PROJ + col] =
                        make_float2(acc[mi][ni][0], acc[mi][ni][1]);
                    *(float2*)&g_Z[(size_t)(r+8)*PROJ + col] =
                        make_float2(acc[mi][ni][2], acc[mi][ni][3]);
                }
            }
    } else {
#pragma unroll
        for (int mi = 0; mi < 2; mi++)
#pragma unroll
            for (int ni = 0; ni < 4; ni++) {
                int col = n0 + wn + ni*8 + cl;
#pragma unroll
                for (int half = 0; half < 2; half++) {
                    int r = m0 + wm + mi*16 + rw + half*8;
                    int seq = r / L, t = r - seq*L;
                    float* op = xout + xoff(axis, seq, t) + col;
                    float2 o = *(const float2*)op;
                    o.x += acc[mi][ni][2*half];
                    o.y += acc[mi][ni][2*half+1];
                    *(float2*)op = o;
                }
            }
    }
}

/* ------- 3. causal conv(K=4)+SiLU + softplus(dt); div-free indexing ---- */
__global__ void k_convdt(const float* __restrict__ Wc, const float* __restrict__ bc,
                         const float* __restrict__ dtb)
{
    int c   = blockIdx.x*256 + threadIdx.x;
    int t   = blockIdx.y;
    int seq = blockIdx.z;
    int L   = gridDim.y;
    if (c >= CONVDIM + NHEADS) return;
    size_t tok = (size_t)seq*L + t;
    if (c < CONVDIM) {
        const float* zp = g_Z + tok*PROJ + DIN + c;
        float acc = bc[c];
        float4 w = *(const float4*)&Wc[c*4];
        if (t >= 3) {
            acc += w.x*zp[-3*PROJ] + w.y*zp[-2*PROJ] + w.z*zp[-PROJ] + w.w*zp[0];
        } else {
            if (t >= 2) acc += w.y*zp[-2*PROJ];
            if (t >= 1) acc += w.z*zp[-PROJ];
            acc += w.w*zp[0];
        }
        g_xBC[tok*CONVDIM + c] = __fdividef(acc, 1.f + __expf(-acc));
    } else {
        int h = c - CONVDIM;
        float v = g_Z[tok*PROJ + DIN + CONVDIM + h] + dtb[h];
        g_dt[tok*NHEADS + h] = (v > 20.f) ? v : log1pf(__expf(v));
    }
}

/* --------- 5. CB stored [l][s]: g_CB[seq][l][s] = C[l].B[s] ------------ */
__global__ void k_cb(int L)
{
    __shared__ __align__(16) float Ct[64][68], Bt[64][68];
    int seq = blockIdx.x;
    int l0 = blockIdx.y*64, s0 = blockIdx.z*64;
    int tid = threadIdx.x;
    int n = tid & 63, r = tid >> 6;
#pragma unroll 4
    for (int i = 0; i < 16; i++) {
        int row = r + 4*i;
        int gl = l0 + row, gs = s0 + row;
        Ct[n][row] = (gl < L) ? g_xBC[(size_t)(seq*L + gl)*CONVDIM + DIN + DSTATE + n] : 0.f;
        Bt[n][row] = (gs < L) ? g_xBC[(size_t)(seq*L + gs)*CONVDIM + DIN + n]          : 0.f;
    }
    __syncthreads();
    int tx = tid & 15, ty = tid >> 4;
    float acc[4][4] = {};
#pragma unroll 8
    for (int k = 0; k < 64; k++) {
        float4 a = *(const float4*)&Ct[k][ty*4];
        float4 b = *(const float4*)&Bt[k][tx*4];
        acc[0][0]+=a.x*b.x; acc[0][1]+=a.x*b.y; acc[0][2]+=a.x*b.z; acc[0][3]+=a.x*b.w;
        acc[1][0]+=a.y*b.x; acc[1][1]+=a.y*b.y; acc[1][2]+=a.y*b.z; acc[1][3]+=a.y*b.w;
        acc[2][0]+=a.z*b.x; acc[2][1]+=a.z*b.y; acc[2][2]+=a.z*b.z; acc[2][3]+=a.z*b.w;
        acc[3][0]+=a.w*b.x; acc[3][1]+=a.w*b.y; acc[3][2]+=a.w*b.z; acc[3][3]+=a.w*b.w;
    }
#pragma unroll
    for (int i = 0; i < 4; i++) {
        int gl = l0 + ty*4 + i;
#pragma unroll
        for (int j = 0; j < 4; j++) {
            int gs = s0 + tx*4 + j;
            if (gl < L && gs < L) g_CB[(size_t)(seq*L + gl)*L + gs] = acc[i][j];
        }
    }
}

/* --- 6. SSD via split-bf16 HMMA (W [l][s] A row-major; X [s][p] .trans) */
#define SSR 72
__global__ void __launch_bounds__(256)
k_ssd(const float* __restrict__ Alog, int L)
{
    __shared__ float cum[192], ecum[192], dts[192];
    __shared__ float uf[64], ub[64], vbuf[64];
    __shared__ __align__(16) __nv_bfloat16 Wh[64][SSR], Wl[64][SSR];
    __shared__ __align__(16) __nv_bfloat16 Xh[64][SSR], Xl[64][SSR];
    int seq = blockIdx.x, h = blockIdx.y, l0 = blockIdx.z*64;
    int tid = threadIdx.x, lane = tid & 31, wid = tid >> 5;
    float A = -expf(Alog[h]);
    int lend = min(l0 + 63, L - 1);

    for (int t = tid; t < L; t += 256) {
        float d = g_dt[(seq*L + t)*NHEADS + h];
        dts[t] = d;
        cum[t] = d*A;
    }
    __syncthreads();
    for (int off = 1; off < L; off <<= 1) {
        float v = 0.f;
        if (tid < L && tid >= off) v = cum[tid - off];
        __syncthreads();
        if (tid < L) cum[tid] += v;
        __syncthreads();
    }
    for (int t = tid; t < L; t += 256) ecum[t] = cum[t] - dts[t]*A;
    __syncthreads();
    if (tid < 64) {
        int gl = l0 + tid;
        uf[tid] = (gl < L) ? __expf(cum[gl] - cum[l0])     : 0.f;
        ub[tid] = (gl < L) ? __expf(ecum[lend] - ecum[gl]) : 0.f;
    }
    __syncthreads();

    int wm = (wid & 3)*16, wn = (wid >> 2)*32;
    int q = lane >> 3, r8 = lane & 7;
    uint32_t sbW = smem_u32(Wh), sbWl = smem_u32(Wl);
    uint32_t sbX = smem_u32(Xh), sbXl = smem_u32(Xl);
    uint32_t aoff = (uint32_t)((wm + (q & 1)*8 + r8)*(SSR*2) + (q >> 1)*16);
    uint32_t brow = (uint32_t)(((q & 1)*8 + r8)*(SSR*2));
    uint32_t bcol = (uint32_t)((wn + (q >> 1)*8)*2);

    int fc = tid & 63, fr = tid >> 6;
    float acc[4][4] = {};

    for (int s0 = 0; s0 < L; s0 += 64) {
        int diag = (s0 == l0);
        if (!diag && tid < 64) {
            int gs = s0 + tid;
            float v = 0.f;
            if (gs < L) {
                v = (s0 < l0) ? __expf(cum[l0] - cum[gs])
                              : __expf(ecum[gs] - ecum[lend]);
                v *= dts[gs];
            }
            vbuf[tid] = v;
        }
#pragma unroll 4
        for (int i = 0; i < 16; i++) {
            int s = fr + 4*i;
            int gs = s0 + s;
            float v = (gs < L) ? g_xBC[(size_t)(seq*L + gs)*CONVDIM + h*HEADP + fc] : 0.f;
            __nv_bfloat16 hh = __float2bfloat16(v);
            Xh[s][fc] = hh;
            Xl[s][fc] = __float2bfloat16(v - __bfloat162float(hh));
        }
        if (!diag) __syncthreads();

        if (diag) {
#pragma unroll 4
            for (int i = 0; i < 16; i++) {
                int lW = fr + 4*i, sW = fc;
                int gl = l0 + lW, gs = s0 + sW;
                float w = 0.f;
                if (gl < L && gs < L) {
                    float cb = g_CB[(size_t)(seq*L + gl)*L + gs];
                    float e;
                    if (gs < gl)       e = __expf(cum[gl] - cum[gs]);
                    else if (gs == gl) e = 2.f;
                    else               e = __expf(ecum[gs] - ecum[gl]);
                    w = cb * e * dts[gs];
                }
                __nv_bfloat16 hh = __float2bfloat16(w);
                Wh[lW][sW] = hh;
                Wl[lW][sW] = __float2bfloat16(w - __bfloat162float(hh));
            }
        } else {
            const float* uu = (s0 < l0) ? uf : ub;
#pragma unroll 4
            for (int i = 0; i < 16; i++) {
                int lW = fr + 4*i, sW = fc;
                int gl = l0 + lW, gs = s0 + sW;
                float w = 0.f;
                if (gl < L && gs < L)
                    w = g_CB[(size_t)(seq*L + gl)*L + gs] * vbuf[sW] * uu[lW];
                __nv_bfloat16 hh = __float2bfloat16(w);
                Wh[lW][sW] = hh;
                Wl[lW][sW] = __float2bfloat16(w - __bfloat162float(hh));
            }
        }
        __syncthreads();
#pragma unroll
        for (int kb = 0; kb < 4; kb++) {
            uint32_t ah[4], al[4];
            ldm4(ah, sbW  + aoff + kb*32);
            ldm4(al, sbWl + aoff + kb*32);
#pragma unroll
            for (int nh = 0; nh < 2; nh++) {
                uint32_t bh[4], bl[4];
                uint32_t bo = brow + kb*16*(SSR*2) + bcol + nh*32;
                ldm4t(bh, sbX  + bo);
                ldm4t(bl, sbXl + bo);
                mma16(acc[nh*2+0], ah, bh[0], bh[1]);
                mma16(acc[nh*2+0], ah, bl[0], bl[1]);
                mma16(acc[nh*2+0], al, bh[0], bh[1]);
                mma16(acc[nh*2+1], ah, bh[2], bh[3]);
                mma16(acc[nh*2+1], ah, bl[2], bl[3]);
                mma16(acc[nh*2+1], al, bh[2], bh[3]);
            }
        }
        __syncthreads();
    }

    int rw = lane >> 2, cl = (lane & 3)*2;
#pragma unroll
    for (int half = 0; half < 2; half++) {
        int gl = l0 + wm + half*8 + rw;
        if (gl < L) {
            float* yp = g_y + (size_t)(seq*L + gl)*DIN + h*HEADP + wn + cl;
#pragma unroll
            for (int nf = 0; nf < 4; nf++)
                *(float2*)&yp[nf*8] = make_float2(acc[nf][2*half], acc[nf][2*half+1]);
        }
    }
}

/* ---------- 7. (y + D*xh) * silu(z), then RMSNorm(512) * gn_w ---------- */
__global__ void k_gate(const float* __restrict__ Dv, const float* __restrict__ gnw)
{
    __shared__ float red[8];
    int tok = blockIdx.x, tid = threadIdx.x;
    float v[2]; float ss = 0.f;
#pragma unroll
    for (int i = 0; i < 2; i++) {
        int d = tid + 256*i;
        float y = g_y[(size_t)tok*DIN + d] + Dv[d >> 6]*g_xBC[(size_t)tok*CONVDIM + d];
        float z = g_Z[(size_t)tok*PROJ + d];
        y *= __fdividef(z, 1.f + __expf(-z));
        v[i] = y; ss += y*y;
    }
#pragma unroll
    for (int o = 16; o; o >>= 1) ss += __shfl_xor_sync(0xffffffffu, ss, o);
    if ((tid & 31) == 0) red[tid >> 5] = ss;
    __syncthreads();
    if (tid < 32) {
        float s = (tid < 8) ? red[tid] : 0.f;
#pragma unroll
        for (int o = 4; o; o >>= 1) s += __shfl_xor_sync(0xffffffffu, s, o);
        if (tid == 0) red[0] = s;
    }
    __syncthreads();
    float r = rsqrtf(red[0]*(1.f/DIN) + 1e-6f);
#pragma unroll
    for (int i = 0; i < 2; i++) {
        int d = tid + 256*i;
        g_y[(size_t)tok*DIN + d] = v[i]*r*gnw[d];
    }
}

/* ----------------------------- host side ------------------------------ */
static __nv_bfloat16 *h_whi, *h_wlo;

static void run_call(float* out, const float* const* P, int li, int axis, int idx)
{
    int L = (axis == 0) ? Tn : NBn;
    int nseq = NTOK / L;
    int lt = (L + 63)/64;

    k_rmsnorm<<<NTOK/8, 256>>>(out, P[0] + li*HID, axis, L);
    k_mma<<<dim3((PROJ + 63)/64, NTOK/128), 256, GSM>>>(0,
        h_whi + (size_t)idx*PROJ*HID, h_wlo + (size_t)idx*PROJ*HID,
        PROJ, HID, 0, nullptr, axis, L);
    k_convdt<<<dim3(3, L, nseq), 256>>>(
        P[2] + li*CONVDIM*4, P[3] + li*CONVDIM, P[4] + li*NHEADS);
    k_cb<<<dim3(nseq, lt, lt), 256>>>(L);
    k_ssd<<<dim3(nseq, NHEADS, lt), 256>>>(P[5] + li*NHEADS, L);
    k_gate<<<NTOK, 256>>>(P[6] + li*NHEADS, P[7] + li*DIN);
    k_mma<<<dim3(HID/64, NTOK/128), 256, GSM>>>(1,
        h_whi + WIN_SZ + (size_t)idx*HID*DIN, h_wlo + WIN_SZ + (size_t)idx*HID*DIN,
        HID, DIN, 1, out, axis, L);
}

extern "C" void kernel_launch(void* const* d_in, const int* in_sizes, int n_in,
                              void* d_out, int out_size)
{
    static int smem_set = 0;
    if (!smem_set) {
        cudaFuncSetAttribute(k_mma, cudaFuncAttributeMaxDynamicSharedMemorySize, GSM);
        smem_set = 1;
    }

    float* out = (float*)d_out;
    cudaMemcpyAsync(out, d_in[0], (size_t)out_size*sizeof(float),
                    cudaMemcpyDeviceToDevice);
    const float* tp[9]; const float* bp[9];
    for (int i = 0; i < 9; i++) {
        tp[i] = (const float*)d_in[1 + i];
        bp[i] = (const float*)d_in[10 + i];
    }
    cudaGetSymbolAddress((void**)&h_whi, g_Whi);
    cudaGetSymbolAddress((void**)&h_wlo, g_Wlo);

    for (int ax = 0; ax < 2; ax++) {
        const float* const* P = ax ? bp : tp;
        for (int li = 0; li < 2; li++) {
            int idx = ax*2 + li;
            k_splitw<<<dim3((PROJ+31)/32, (HID+31)/32), dim3(32,8)>>>(
                P[1] + li*HID*PROJ,
                h_whi + (size_t)idx*PROJ*HID, h_wlo + (size_t)idx*PROJ*HID, HID, PROJ);
            k_splitw<<<dim3((HID+31)/32, (DIN+31)/32), dim3(32,8)>>>(
                P[8] + li*DIN*HID,
                h_whi + WIN_SZ + (size_t)idx*HID*DIN, h_wlo + WIN_SZ + (size_t)idx*HID*DIN,
                DIN, HID);
        }
    }

    run_call(out, tp, 0, 0, 0);
    run_call(out, bp, 0, 1, 2);
    run_call(out, tp, 1, 0, 1);
    run_call(out, bp, 1, 1, 3);
}